// round 1
// baseline (speedup 1.0000x reference)
#include <cuda_runtime.h>
#include <math.h>

#define B_ 2
#define S_ 2048
#define HID_ 2048
#define NH_ 32
#define NKV_ 8
#define HD_ 64
#define BS_ (B_*S_)

// ---------------- scratch (static device globals; no allocation) ----------------
__device__ float g_q[(size_t)BS_*2048];      // [(b*S+s)*2048 + h*64 + d]
__device__ float g_k[(size_t)BS_*512];       // [(b*S+s)*512 + kv*64 + d]
__device__ float g_v[(size_t)BS_*512];
__device__ float g_ao[(size_t)B_*NH_*S_*128]; // [((b*32+h)*S + s)*128 + d]
__device__ float g_attn[(size_t)BS_*2048];   // [(b*S+s)*2048 + h*128 + d]
__device__ float g_lam;

// ---------------- lambda scalar ----------------
__global__ void lam_kernel(const float* __restrict__ lq1, const float* __restrict__ lk1,
                           const float* __restrict__ lq2, const float* __restrict__ lk2) {
    int t = threadIdx.x;  // 32 threads
    float s1 = lq1[t]*lk1[t] + lq1[t+32]*lk1[t+32];
    float s2 = lq2[t]*lk2[t] + lq2[t+32]*lk2[t+32];
    #pragma unroll
    for (int off = 16; off >= 1; off >>= 1) {
        s1 += __shfl_xor_sync(0xffffffffu, s1, off);
        s2 += __shfl_xor_sync(0xffffffffu, s2, off);
    }
    if (t == 0) {
        float li = 0.8f - 0.6f*expf(-0.3f);
        g_lam = expf(s1) - expf(s2) + li;
    }
}

// ---------------- generic C = A @ W^T (A:[M,K], W:[N,K], row-major) ----------------
__global__ void __launch_bounds__(256) gemm_nt_kernel(
    const float* __restrict__ A, const float* __restrict__ W,
    float* __restrict__ C, int M, int N, int K) {
    __shared__ float As[64][17];
    __shared__ float Ws[64][17];
    const int tid = threadIdx.x;
    const int tx = tid & 15, ty = tid >> 4;
    const int m0 = blockIdx.y << 6, n0 = blockIdx.x << 6;
    const int lrow = tid >> 2, lk = (tid & 3) << 2;
    const float* Ap = A + (size_t)(m0 + lrow) * K + lk;
    const float* Wp = W + (size_t)(n0 + lrow) * K + lk;

    float acc[4][4];
    #pragma unroll
    for (int i = 0; i < 4; i++)
        #pragma unroll
        for (int j = 0; j < 4; j++) acc[i][j] = 0.f;

    for (int k0 = 0; k0 < K; k0 += 16) {
        float4 av = *(const float4*)(Ap + k0);
        float4 wv = *(const float4*)(Wp + k0);
        As[lrow][lk+0] = av.x; As[lrow][lk+1] = av.y; As[lrow][lk+2] = av.z; As[lrow][lk+3] = av.w;
        Ws[lrow][lk+0] = wv.x; Ws[lrow][lk+1] = wv.y; Ws[lrow][lk+2] = wv.z; Ws[lrow][lk+3] = wv.w;
        __syncthreads();
        #pragma unroll
        for (int k = 0; k < 16; k++) {
            float af[4], wf[4];
            #pragma unroll
            for (int i = 0; i < 4; i++) af[i] = As[ty*4+i][k];
            #pragma unroll
            for (int j = 0; j < 4; j++) wf[j] = Ws[tx*4+j][k];
            #pragma unroll
            for (int i = 0; i < 4; i++)
                #pragma unroll
                for (int j = 0; j < 4; j++) acc[i][j] += af[i]*wf[j];
        }
        __syncthreads();
    }
    #pragma unroll
    for (int i = 0; i < 4; i++) {
        float4 cv = make_float4(acc[i][0], acc[i][1], acc[i][2], acc[i][3]);
        *(float4*)&C[(size_t)(m0 + ty*4 + i)*N + n0 + tx*4] = cv;
    }
}

// ---------------- RoPE in-place on [BS, nheads*64] ----------------
__global__ void rope_kernel(float* __restrict__ x, const float* __restrict__ cs,
                            const float* __restrict__ sn, int nheads, int total) {
    int idx = blockIdx.x*blockDim.x + threadIdx.x;
    if (idx >= total) return;
    int d  = idx & 31;
    int h  = (idx >> 5) % nheads;
    int bs = idx / (32*nheads);
    float* row = x + (size_t)bs*nheads*64 + h*64;
    float c0 = cs[(size_t)bs*64 + d],      s0 = sn[(size_t)bs*64 + d];
    float c1 = cs[(size_t)bs*64 + d + 32], s1 = sn[(size_t)bs*64 + d + 32];
    float x0 = row[d], x1 = row[d+32];
    row[d]    = x0*c0 - x1*s0;
    row[d+32] = x1*c1 + x0*s1;
}

// ---------------- flash attention, causal, d_eff = 128 via v-concat ----------------
// grid: (qtile=32, h=32, b=2), 256 threads, dynamic smem 67072B
__global__ void __launch_bounds__(256) attn_kernel(
    const float* __restrict__ q, const float* __restrict__ k,
    const float* __restrict__ v, float* __restrict__ ao) {
    extern __shared__ float smem[];
    float (*Qs)[65]  = (float(*)[65])smem;                 // 64x65
    float (*Ks)[65]  = (float(*)[65])(smem + 64*65);       // 64x65 (reused for P)
    float (*Vs)[132] = (float(*)[132])(smem + 2*64*65);    // 64x132

    const int tid = threadIdx.x;
    const int tx = tid & 15, ty = tid >> 4;
    const int qt = blockIdx.x, h = blockIdx.y, b = blockIdx.z;
    const int kvq = h >> 2;                 // K head after repeat
    const int j1 = (h & 15) >> 2;           // V first half kv head
    const int j2 = j1 + 4;                  // V second half kv head

    // load Q tile, pre-scaled by 1/sqrt(64)
    {
        const size_t qbase = ((size_t)b*S_ + (size_t)qt*64)*2048 + (size_t)h*64;
        for (int u = tid; u < 1024; u += 256) {
            int row = u >> 4, d = (u & 15) << 2;
            float4 qv = *(const float4*)(q + qbase + (size_t)row*2048 + d);
            Qs[row][d]   = qv.x*0.125f; Qs[row][d+1] = qv.y*0.125f;
            Qs[row][d+2] = qv.z*0.125f; Qs[row][d+3] = qv.w*0.125f;
        }
    }

    float m[4], l[4], O[4][8];
    #pragma unroll
    for (int i = 0; i < 4; i++) {
        m[i] = -1e30f; l[i] = 0.f;
        #pragma unroll
        for (int j = 0; j < 8; j++) O[i][j] = 0.f;
    }

    for (int kt = 0; kt <= qt; kt++) {
        __syncthreads();  // previous iteration consumers of Ks/Vs done (also covers Q load)
        {
            const size_t kbase = ((size_t)b*S_ + (size_t)kt*64)*512 + (size_t)kvq*64;
            for (int u = tid; u < 1024; u += 256) {
                int row = u >> 4, d = (u & 15) << 2;
                float4 kv4 = *(const float4*)(k + kbase + (size_t)row*512 + d);
                Ks[row][d]   = kv4.x; Ks[row][d+1] = kv4.y;
                Ks[row][d+2] = kv4.z; Ks[row][d+3] = kv4.w;
            }
            const size_t vbase = ((size_t)b*S_ + (size_t)kt*64)*512;
            for (int u = tid; u < 2048; u += 256) {
                int row = u >> 5, d = (u & 31) << 2;
                int kvh = (d < 64) ? j1 : j2;
                float4 vv = *(const float4*)(v + vbase + (size_t)row*512 + kvh*64 + (d & 63));
                Vs[row][d]   = vv.x; Vs[row][d+1] = vv.y;
                Vs[row][d+2] = vv.z; Vs[row][d+3] = vv.w;
            }
        }
        __syncthreads();

        // scores: 4x4 per thread
        float sc[4][4];
        #pragma unroll
        for (int i = 0; i < 4; i++)
            #pragma unroll
            for (int j = 0; j < 4; j++) sc[i][j] = 0.f;
        #pragma unroll 4
        for (int d = 0; d < 64; d++) {
            float af[4], kf[4];
            #pragma unroll
            for (int i = 0; i < 4; i++) af[i] = Qs[ty*4+i][d];
            #pragma unroll
            for (int j = 0; j < 4; j++) kf[j] = Ks[tx*4+j][d];
            #pragma unroll
            for (int i = 0; i < 4; i++)
                #pragma unroll
                for (int j = 0; j < 4; j++) sc[i][j] += af[i]*kf[j];
        }
        if (kt == qt) {  // causal mask inside diagonal tile
            #pragma unroll
            for (int i = 0; i < 4; i++)
                #pragma unroll
                for (int j = 0; j < 4; j++)
                    if (tx*4+j > ty*4+i) sc[i][j] = -1e30f;
        }

        // online softmax update
        float p[4][4];
        #pragma unroll
        for (int i = 0; i < 4; i++) {
            float rm = sc[i][0];
            #pragma unroll
            for (int j = 1; j < 4; j++) rm = fmaxf(rm, sc[i][j]);
            #pragma unroll
            for (int off = 8; off >= 1; off >>= 1)
                rm = fmaxf(rm, __shfl_xor_sync(0xffffffffu, rm, off));
            float mn = fmaxf(m[i], rm);
            float f  = __expf(m[i] - mn);
            float rs = 0.f;
            #pragma unroll
            for (int j = 0; j < 4; j++) { p[i][j] = __expf(sc[i][j] - mn); rs += p[i][j]; }
            #pragma unroll
            for (int off = 8; off >= 1; off >>= 1)
                rs += __shfl_xor_sync(0xffffffffu, rs, off);
            l[i] = l[i]*f + rs;
            m[i] = mn;
            #pragma unroll
            for (int j = 0; j < 8; j++) O[i][j] *= f;
        }

        __syncthreads();  // done reading Ks as K
        #pragma unroll
        for (int i = 0; i < 4; i++)
            #pragma unroll
            for (int j = 0; j < 4; j++)
                Ks[ty*4+i][tx*4+j] = p[i][j];
        __syncthreads();  // P visible

        // O += P @ V  (thread: rows ty*4..+3, cols tx + 16*j)
        #pragma unroll 4
        for (int c = 0; c < 64; c++) {
            float pf[4], vf[8];
            #pragma unroll
            for (int i = 0; i < 4; i++) pf[i] = Ks[ty*4+i][c];
            #pragma unroll
            for (int j = 0; j < 8; j++) vf[j] = Vs[c][tx + 16*j];
            #pragma unroll
            for (int i = 0; i < 4; i++)
                #pragma unroll
                for (int j = 0; j < 8; j++) O[i][j] += pf[i]*vf[j];
        }
    }

    #pragma unroll
    for (int i = 0; i < 4; i++) {
        float inv = 1.0f / l[i];
        size_t base = (((size_t)b*NH_ + h)*S_ + (size_t)qt*64 + ty*4 + i)*128;
        #pragma unroll
        for (int j = 0; j < 8; j++)
            ao[base + tx + 16*j] = O[i][j]*inv;
    }
}

// ---------------- differential combine + RMS norm ----------------
// grid: B*S*16 blocks, 128 threads
__global__ void __launch_bounds__(128) diff_rms_kernel(
    const float* __restrict__ ao, float* __restrict__ out) {
    __shared__ float red[4];
    int blk = blockIdx.x;
    int h  = blk & 15;
    int bs = blk >> 4;          // b*S + s
    int b  = bs >> 11;          // S = 2048
    int s  = bs & 2047;
    int t  = threadIdx.x;
    const float* a1 = ao + (((size_t)b*32 + h)*S_ + s)*128;
    const float* a2 = ao + (((size_t)b*32 + h + 16)*S_ + s)*128;
    float lam = g_lam;
    float x = a1[t] - lam*a2[t];
    float ss = x*x;
    #pragma unroll
    for (int off = 16; off >= 1; off >>= 1) ss += __shfl_xor_sync(0xffffffffu, ss, off);
    if ((t & 31) == 0) red[t >> 5] = ss;
    __syncthreads();
    float tot = red[0] + red[1] + red[2] + red[3];
    float r = rsqrtf(tot*(1.0f/128.0f) + 1e-6f);
    float li = 0.8f - 0.6f*expf(-0.3f);
    out[(size_t)bs*2048 + h*128 + t] = (1.0f - li) * x * r;
}

// ---------------- launch ----------------
extern "C" void kernel_launch(void* const* d_in, const int* in_sizes, int n_in,
                              void* d_out, int out_size) {
    const float* hs  = (const float*)d_in[0];
    const float* cs  = (const float*)d_in[1];
    const float* sn  = (const float*)d_in[2];
    // d_in[3] = attention_mask (pure causal; handled analytically)
    const float* wq  = (const float*)d_in[4];
    const float* wk  = (const float*)d_in[5];
    const float* wv  = (const float*)d_in[6];
    const float* wo  = (const float*)d_in[7];
    const float* lq1 = (const float*)d_in[8];
    const float* lk1 = (const float*)d_in[9];
    const float* lq2 = (const float*)d_in[10];
    const float* lk2 = (const float*)d_in[11];
    float* out = (float*)d_out;

    float *qb, *kb, *vb, *aob, *atb;
    cudaGetSymbolAddress((void**)&qb,  g_q);
    cudaGetSymbolAddress((void**)&kb,  g_k);
    cudaGetSymbolAddress((void**)&vb,  g_v);
    cudaGetSymbolAddress((void**)&aob, g_ao);
    cudaGetSymbolAddress((void**)&atb, g_attn);

    const int attn_smem = (2*64*65 + 64*132) * 4;  // 67072 bytes
    cudaFuncSetAttribute(attn_kernel, cudaFuncAttributeMaxDynamicSharedMemorySize, attn_smem);

    lam_kernel<<<1, 32>>>(lq1, lk1, lq2, lk2);

    dim3 gq(2048/64, BS_/64);
    gemm_nt_kernel<<<gq, 256>>>(hs, wq, qb, BS_, 2048, 2048);
    dim3 gkv(512/64, BS_/64);
    gemm_nt_kernel<<<gkv, 256>>>(hs, wk, kb, BS_, 512, 2048);
    gemm_nt_kernel<<<gkv, 256>>>(hs, wv, vb, BS_, 512, 2048);

    int tq = BS_ * NH_ * 32;
    rope_kernel<<<(tq + 255)/256, 256>>>(qb, cs, sn, NH_, tq);
    int tk = BS_ * NKV_ * 32;
    rope_kernel<<<(tk + 255)/256, 256>>>(kb, cs, sn, NKV_, tk);

    dim3 ga(S_/64, NH_, B_);
    attn_kernel<<<ga, 256, attn_smem>>>(qb, kb, vb, aob);

    diff_rms_kernel<<<BS_*16, 128>>>(aob, atb);

    dim3 go(2048/64, BS_/64);
    gemm_nt_kernel<<<go, 256>>>(atb, wo, out, BS_, 2048, 2048);
}

// round 2
// speedup vs baseline: 1.7611x; 1.7611x over previous
#include <cuda_runtime.h>
#include <math.h>
#include <stdint.h>

#define B_ 2
#define S_ 2048
#define HID_ 2048
#define NH_ 32
#define NKV_ 8
#define HD_ 64
#define BS_ (B_*S_)

// ---------------- scratch ----------------
__device__ float g_q[(size_t)BS_*2048];
__device__ float g_k[(size_t)BS_*512];
__device__ float g_v[(size_t)BS_*512];
__device__ float g_ao[(size_t)B_*NH_*S_*128];
__device__ float g_attn[(size_t)BS_*2048];
__device__ float g_lam;

// ---------------- mma helpers ----------------
__device__ __forceinline__ uint32_t f2tf32(float x) {
    uint32_t y;
    asm("cvt.rna.tf32.f32 %0, %1;" : "=r"(y) : "f"(x));
    return y;
}
__device__ __forceinline__ void mma_tf32(float* d, const uint32_t* a, const uint32_t* b) {
    asm volatile(
        "mma.sync.aligned.m16n8k8.row.col.f32.tf32.tf32.f32 "
        "{%0,%1,%2,%3}, {%4,%5,%6,%7}, {%8,%9}, {%0,%1,%2,%3};\n"
        : "+f"(d[0]), "+f"(d[1]), "+f"(d[2]), "+f"(d[3])
        : "r"(a[0]), "r"(a[1]), "r"(a[2]), "r"(a[3]), "r"(b[0]), "r"(b[1]));
}

// ---------------- lambda scalar ----------------
__global__ void lam_kernel(const float* __restrict__ lq1, const float* __restrict__ lk1,
                           const float* __restrict__ lq2, const float* __restrict__ lk2) {
    int t = threadIdx.x;
    float s1 = lq1[t]*lk1[t] + lq1[t+32]*lk1[t+32];
    float s2 = lq2[t]*lk2[t] + lq2[t+32]*lk2[t+32];
    #pragma unroll
    for (int off = 16; off >= 1; off >>= 1) {
        s1 += __shfl_xor_sync(0xffffffffu, s1, off);
        s2 += __shfl_xor_sync(0xffffffffu, s2, off);
    }
    if (t == 0) {
        float li = 0.8f - 0.6f*expf(-0.3f);
        g_lam = expf(s1) - expf(s2) + li;
    }
}

// ---------------- tf32 tensor-core GEMM: C = A @ W^T ----------------
// A:[M,K] row-major, W:[N,K] row-major. Block tile 128x128, kc=32, 256 thr.
__global__ void __launch_bounds__(256) gemm_tc(
    const float* __restrict__ A, const float* __restrict__ W,
    float* __restrict__ C, int M, int N, int K) {
    __shared__ uint32_t Asm[4096];  // 8 mtiles x 4 ktiles x 32 lanes x 4 regs
    __shared__ uint32_t Bsm[4096];  // 16 ntiles x 4 ktiles x 32 lanes x 2 regs
    const int tid = threadIdx.x, lane = tid & 31, warp = tid >> 5;
    const int wm = warp >> 2, wn = warp & 3;
    const int m0 = blockIdx.y << 7, n0 = blockIdx.x << 7;
    const int lrow = tid >> 3, lk = (tid & 7) << 2;

    float acc[4][4][4];
    #pragma unroll
    for (int mt = 0; mt < 4; mt++)
        #pragma unroll
        for (int nt = 0; nt < 4; nt++)
            #pragma unroll
            for (int r = 0; r < 4; r++) acc[mt][nt][r] = 0.f;

    for (int k0 = 0; k0 < K; k0 += 32) {
        __syncthreads();
        #pragma unroll
        for (int p = 0; p < 4; p++) {
            int row = p*32 + lrow;
            float4 av = *(const float4*)(A + (size_t)(m0+row)*K + k0 + lk);
            int mt = row >> 4, r = row & 15;
            #pragma unroll
            for (int i = 0; i < 4; i++) {
                int kk = lk + i, ktile = kk >> 3, t8 = kk & 7;
                Asm[((mt*4+ktile)*32 + (r&7)*4 + (t8&3))*4 + (r>>3) + 2*(t8>>2)] =
                    f2tf32(((const float*)&av)[i]);
            }
            float4 wv = *(const float4*)(W + (size_t)(n0+row)*K + k0 + lk);
            int ntg = row >> 3, g = row & 7;
            #pragma unroll
            for (int i = 0; i < 4; i++) {
                int kk = lk + i, ktile = kk >> 3, t8 = kk & 7;
                Bsm[((ntg*4+ktile)*32 + g*4 + (t8&3))*2 + (t8>>2)] =
                    f2tf32(((const float*)&wv)[i]);
            }
        }
        __syncthreads();
        #pragma unroll
        for (int kt = 0; kt < 4; kt++) {
            uint32_t af[4][4], bf[4][2];
            #pragma unroll
            for (int mt = 0; mt < 4; mt++)
                *(uint4*)af[mt] = *(const uint4*)&Asm[(((wm*4+mt)*4+kt)*32 + lane)*4];
            #pragma unroll
            for (int nt = 0; nt < 4; nt++)
                *(uint2*)bf[nt] = *(const uint2*)&Bsm[(((wn*4+nt)*4+kt)*32 + lane)*2];
            #pragma unroll
            for (int mt = 0; mt < 4; mt++)
                #pragma unroll
                for (int nt = 0; nt < 4; nt++)
                    mma_tf32(acc[mt][nt], af[mt], bf[nt]);
        }
    }
    const int g = lane >> 2, t = lane & 3;
    #pragma unroll
    for (int mt = 0; mt < 4; mt++) {
        #pragma unroll
        for (int nt = 0; nt < 4; nt++) {
            size_t r0 = (size_t)(m0 + wm*64 + mt*16 + g)*N + n0 + wn*32 + nt*8 + 2*t;
            *(float2*)&C[r0]               = make_float2(acc[mt][nt][0], acc[mt][nt][1]);
            *(float2*)&C[r0 + (size_t)8*N] = make_float2(acc[mt][nt][2], acc[mt][nt][3]);
        }
    }
}

// ---------------- RoPE ----------------
__global__ void rope_kernel(float* __restrict__ x, const float* __restrict__ cs,
                            const float* __restrict__ sn, int nheads, int total) {
    int idx = blockIdx.x*blockDim.x + threadIdx.x;
    if (idx >= total) return;
    int d  = idx & 31;
    int h  = (idx >> 5) % nheads;
    int bs = idx / (32*nheads);
    float* row = x + (size_t)bs*nheads*64 + h*64;
    float c0 = cs[(size_t)bs*64 + d],      s0 = sn[(size_t)bs*64 + d];
    float c1 = cs[(size_t)bs*64 + d + 32], s1 = sn[(size_t)bs*64 + d + 32];
    float x0 = row[d], x1 = row[d+32];
    row[d]    = x0*c0 - x1*s0;
    row[d+32] = x1*c1 + x0*s1;
}

// ---------------- tf32 flash attention ----------------
// grid: (32 qtiles, 32 heads, 2 batch), 128 threads, 80KB dyn smem
__global__ void __launch_bounds__(128) attn_tc(
    const float* __restrict__ q, const float* __restrict__ k,
    const float* __restrict__ v, float* __restrict__ ao) {
    extern __shared__ uint32_t sm[];
    uint32_t* Qsm = sm;            // 4 mt x 8 kt x 32 x 4 = 4096
    uint32_t* Ksm = sm + 4096;     // 8 nt x 8 kt x 32 x 2 = 4096
    uint32_t* Vsm = sm + 8192;     // 16 nt x 8 kt x 32 x 2 = 8192
    uint32_t* Psm = sm + 16384;    // 4 warps x 1024

    const int tid = threadIdx.x, lane = tid & 31, w = tid >> 5;
    const int g = lane >> 2, t = lane & 3;
    const int qt = blockIdx.x, h = blockIdx.y, b = blockIdx.z;
    const int kvq = h >> 2;
    const int j1 = (h & 15) >> 2, j2 = j1 + 4;

    {   // stage Q (pre-scaled by 1/8)
        const float* qp = q + ((size_t)b*S_ + (size_t)qt*64)*2048 + (size_t)h*64;
        #pragma unroll
        for (int u = 0; u < 8; u++) {
            int idx = u*128 + tid;
            int row = idx >> 4, kl = (idx & 15) << 2;
            float4 val = *(const float4*)(qp + (size_t)row*2048 + kl);
            int mt = row >> 4, r = row & 15;
            #pragma unroll
            for (int i = 0; i < 4; i++) {
                int kk = kl + i, ktile = kk >> 3, t8 = kk & 7;
                Qsm[((mt*8+ktile)*32 + (r&7)*4 + (t8&3))*4 + (r>>3) + 2*(t8>>2)] =
                    f2tf32(((const float*)&val)[i] * 0.125f);
            }
        }
    }

    float m_[2], l_[2], O[16][4];
    m_[0] = m_[1] = -1e30f; l_[0] = l_[1] = 0.f;
    #pragma unroll
    for (int nt = 0; nt < 16; nt++)
        #pragma unroll
        for (int r = 0; r < 4; r++) O[nt][r] = 0.f;

    for (int kt = 0; kt <= qt; kt++) {
        __syncthreads();
        {   // stage K
            const float* kp = k + ((size_t)b*S_ + (size_t)kt*64)*512 + kvq*64;
            #pragma unroll
            for (int u = 0; u < 8; u++) {
                int idx = u*128 + tid;
                int row = idx >> 4, kl = (idx & 15) << 2;
                float4 val = *(const float4*)(kp + (size_t)row*512 + kl);
                int ntg = row >> 3, gg = row & 7;
                #pragma unroll
                for (int i = 0; i < 4; i++) {
                    int kk = kl + i, ktile = kk >> 3, t8 = kk & 7;
                    Ksm[((ntg*8+ktile)*32 + gg*4 + (t8&3))*2 + (t8>>2)] =
                        f2tf32(((const float*)&val)[i]);
                }
            }
            // stage V (concat trick: cols 0..63 from head j1, 64..127 from j2)
            const float* vp = v + ((size_t)b*S_ + (size_t)kt*64)*512;
            #pragma unroll
            for (int u = 0; u < 16; u++) {
                int idx = u*128 + tid;
                int row = idx >> 5, c4 = (idx & 31) << 2;
                int kvh = (c4 < 64) ? j1 : j2;
                float4 val = *(const float4*)(vp + (size_t)row*512 + kvh*64 + (c4 & 63));
                int ktile = row >> 3, t8 = row & 7;
                #pragma unroll
                for (int i = 0; i < 4; i++) {
                    int c = c4 + i, ntg = c >> 3, gg = c & 7;
                    Vsm[((ntg*8+ktile)*32 + gg*4 + (t8&3))*2 + (t8>>2)] =
                        f2tf32(((const float*)&val)[i]);
                }
            }
        }
        __syncthreads();

        // scores S = Q K^T (warp w owns rows w*16..w*16+15)
        float s[8][4];
        #pragma unroll
        for (int nt = 0; nt < 8; nt++)
            #pragma unroll
            for (int r = 0; r < 4; r++) s[nt][r] = 0.f;
        #pragma unroll
        for (int ktile = 0; ktile < 8; ktile++) {
            uint32_t af[4];
            *(uint4*)af = *(const uint4*)&Qsm[((w*8+ktile)*32 + lane)*4];
            #pragma unroll
            for (int nt = 0; nt < 8; nt++) {
                uint32_t bf[2];
                *(uint2*)bf = *(const uint2*)&Ksm[((nt*8+ktile)*32 + lane)*2];
                mma_tf32(s[nt], af, bf);
            }
        }
        if (kt == qt) {
            #pragma unroll
            for (int nt = 0; nt < 8; nt++)
                #pragma unroll
                for (int rr = 0; rr < 2; rr++)
                    #pragma unroll
                    for (int cc = 0; cc < 2; cc++)
                        if (nt*8 + 2*t + cc > w*16 + g + rr*8)
                            s[nt][rr*2+cc] = -1e30f;
        }

        // online softmax (rows g / g+8; quad-lane reductions)
        #pragma unroll
        for (int rr = 0; rr < 2; rr++) {
            float rm = -1e30f;
            #pragma unroll
            for (int nt = 0; nt < 8; nt++)
                rm = fmaxf(rm, fmaxf(s[nt][rr*2], s[nt][rr*2+1]));
            rm = fmaxf(rm, __shfl_xor_sync(0xffffffffu, rm, 1));
            rm = fmaxf(rm, __shfl_xor_sync(0xffffffffu, rm, 2));
            float mn = fmaxf(m_[rr], rm);
            float f  = __expf(m_[rr] - mn);
            float rs = 0.f;
            #pragma unroll
            for (int nt = 0; nt < 8; nt++) {
                s[nt][rr*2]   = __expf(s[nt][rr*2]   - mn);
                s[nt][rr*2+1] = __expf(s[nt][rr*2+1] - mn);
                rs += s[nt][rr*2] + s[nt][rr*2+1];
            }
            rs += __shfl_xor_sync(0xffffffffu, rs, 1);
            rs += __shfl_xor_sync(0xffffffffu, rs, 2);
            l_[rr] = l_[rr]*f + rs;
            m_[rr] = mn;
            #pragma unroll
            for (int nt = 0; nt < 16; nt++) { O[nt][rr*2] *= f; O[nt][rr*2+1] *= f; }
        }

        // write P to per-warp smem in A-fragment layout
        #pragma unroll
        for (int nt = 0; nt < 8; nt++)
            #pragma unroll
            for (int rr = 0; rr < 2; rr++)
                #pragma unroll
                for (int cc = 0; cc < 2; cc++) {
                    int cP = nt*8 + 2*t + cc;
                    int t8 = cP & 7;
                    Psm[w*1024 + (nt*32 + g*4 + (t8&3))*4 + rr + 2*(t8>>2)] =
                        f2tf32(s[nt][rr*2+cc]);
                }
        __syncwarp();

        // O += P @ V
        #pragma unroll
        for (int ktile = 0; ktile < 8; ktile++) {
            uint32_t pf[4];
            *(uint4*)pf = *(const uint4*)&Psm[w*1024 + (ktile*32 + lane)*4];
            #pragma unroll
            for (int nt = 0; nt < 16; nt++) {
                uint32_t bf[2];
                *(uint2*)bf = *(const uint2*)&Vsm[((nt*8+ktile)*32 + lane)*2];
                mma_tf32(O[nt], pf, bf);
            }
        }
    }

    #pragma unroll
    for (int rr = 0; rr < 2; rr++) {
        float inv = 1.0f / l_[rr];
        size_t base = (((size_t)b*NH_ + h)*S_ + (size_t)qt*64 + w*16 + g + rr*8)*128;
        #pragma unroll
        for (int nt = 0; nt < 16; nt++)
            *(float2*)&ao[base + nt*8 + 2*t] =
                make_float2(O[nt][rr*2]*inv, O[nt][rr*2+1]*inv);
    }
}

// ---------------- differential combine + RMS norm ----------------
__global__ void __launch_bounds__(128) diff_rms_kernel(
    const float* __restrict__ ao, float* __restrict__ out) {
    __shared__ float red[4];
    int blk = blockIdx.x;
    int h  = blk & 15;
    int bs = blk >> 4;
    int b  = bs >> 11;
    int s  = bs & 2047;
    int t  = threadIdx.x;
    const float* a1 = ao + (((size_t)b*32 + h)*S_ + s)*128;
    const float* a2 = ao + (((size_t)b*32 + h + 16)*S_ + s)*128;
    float lam = g_lam;
    float x = a1[t] - lam*a2[t];
    float ss = x*x;
    #pragma unroll
    for (int off = 16; off >= 1; off >>= 1) ss += __shfl_xor_sync(0xffffffffu, ss, off);
    if ((t & 31) == 0) red[t >> 5] = ss;
    __syncthreads();
    float tot = red[0] + red[1] + red[2] + red[3];
    float r = rsqrtf(tot*(1.0f/128.0f) + 1e-6f);
    float li = 0.8f - 0.6f*expf(-0.3f);
    out[(size_t)bs*2048 + h*128 + t] = (1.0f - li) * x * r;
}

// ---------------- launch ----------------
extern "C" void kernel_launch(void* const* d_in, const int* in_sizes, int n_in,
                              void* d_out, int out_size) {
    const float* hs  = (const float*)d_in[0];
    const float* cs  = (const float*)d_in[1];
    const float* sn  = (const float*)d_in[2];
    const float* wq  = (const float*)d_in[4];
    const float* wk  = (const float*)d_in[5];
    const float* wv  = (const float*)d_in[6];
    const float* wo  = (const float*)d_in[7];
    const float* lq1 = (const float*)d_in[8];
    const float* lk1 = (const float*)d_in[9];
    const float* lq2 = (const float*)d_in[10];
    const float* lk2 = (const float*)d_in[11];
    float* out = (float*)d_out;

    float *qb, *kb, *vb, *aob, *atb;
    cudaGetSymbolAddress((void**)&qb,  g_q);
    cudaGetSymbolAddress((void**)&kb,  g_k);
    cudaGetSymbolAddress((void**)&vb,  g_v);
    cudaGetSymbolAddress((void**)&aob, g_ao);
    cudaGetSymbolAddress((void**)&atb, g_attn);

    const int attn_smem = 20480 * 4;  // 80KB
    cudaFuncSetAttribute(attn_tc, cudaFuncAttributeMaxDynamicSharedMemorySize, attn_smem);

    lam_kernel<<<1, 32>>>(lq1, lk1, lq2, lk2);

    dim3 gq(2048/128, BS_/128);
    gemm_tc<<<gq, 256>>>(hs, wq, qb, BS_, 2048, 2048);
    dim3 gkv(512/128, BS_/128);
    gemm_tc<<<gkv, 256>>>(hs, wk, kb, BS_, 512, 2048);
    gemm_tc<<<gkv, 256>>>(hs, wv, vb, BS_, 512, 2048);

    int tq = BS_ * NH_ * 32;
    rope_kernel<<<(tq + 255)/256, 256>>>(qb, cs, sn, NH_, tq);
    int tk = BS_ * NKV_ * 32;
    rope_kernel<<<(tk + 255)/256, 256>>>(kb, cs, sn, NKV_, tk);

    dim3 ga(S_/64, NH_, B_);
    attn_tc<<<ga, 128, attn_smem>>>(qb, kb, vb, aob);

    diff_rms_kernel<<<BS_*16, 128>>>(aob, atb);

    dim3 go(2048/128, BS_/128);
    gemm_tc<<<go, 256>>>(atb, wo, out, BS_, 2048, 2048);
}